// round 15
// baseline (speedup 1.0000x reference)
#include <cuda_runtime.h>
#include <cuda_bf16.h>

// Problem constants
#define NTOT 10000
#define BB   4096
#define DD   512

// -------- scratch (device globals; no allocation allowed) --------
__device__ int   g_counts[NTOT];
__device__ int   g_offsets[NTOT];
__device__ int   g_perm[BB];
__device__ int   g_ulist[BB];        // compact sorted unique values (U entries)
__device__ int   g_U;
__device__ float g_s[BB];            // per-unique sum of ||y_i||^2
__device__ float g_c[BB];            // per-unique count (float)
__device__ float g_msepart[BB];
__device__ float g_partM[1024];
__device__ float g_partC[1024];
__device__ unsigned g_tilecount;     // reset by k_aggr each replay
__device__ __align__(16) __nv_bfloat16 g_Zb[(size_t)BB * DD];  // aggregated embeddings

// ========== K1: fused preprocessing (single block, shuffle scans, smem sort) ==========
#define PREP_SCNT 0
#define PREP_SIDX (NTOT)
#define PREP_SPERM (NTOT + BB)
#define PREP_SMEM ((NTOT + 2 * BB) * 4)

__global__ __launch_bounds__(1024, 1) void k_prep(const int* __restrict__ idx) {
    extern __shared__ int psm[];
    int* scnt  = psm + PREP_SCNT;    // counts, then reused as scatter cursors
    int* sidx  = psm + PREP_SIDX;
    int* sperm = psm + PREP_SPERM;
    __shared__ int swsum[32], swsum2[32];

    int t = threadIdx.x;
    int lane = t & 31, w = t >> 5;

#pragma unroll
    for (int k = 0; k < 10; k++) {
        int i = t + k * 1024;
        if (i < NTOT) scnt[i] = 0;
    }
#pragma unroll
    for (int k = 0; k < 4; k++) sidx[t + k * 1024] = idx[t + k * 1024];
    __syncthreads();

#pragma unroll
    for (int k = 0; k < 4; k++) atomicAdd(&scnt[sidx[t + k * 1024]], 1);
    __syncthreads();

    int base = t * 10;
    int c[10];
    int sum = 0, usum = 0;
#pragma unroll
    for (int k = 0; k < 10; k++) {
        int v = (base + k < NTOT) ? scnt[base + k] : 0;
        c[k] = v; sum += v; usum += (v > 0);
    }

    int inc = sum, inc2 = usum;
#pragma unroll
    for (int off = 1; off < 32; off <<= 1) {
        int v  = __shfl_up_sync(0xffffffffu, inc,  off);
        int v2 = __shfl_up_sync(0xffffffffu, inc2, off);
        if (lane >= off) { inc += v; inc2 += v2; }
    }
    if (lane == 31) { swsum[w] = inc; swsum2[w] = inc2; }
    __syncthreads();
    if (w == 0) {
        int v  = swsum[lane];
        int v2 = swsum2[lane];
#pragma unroll
        for (int off = 1; off < 32; off <<= 1) {
            int a  = __shfl_up_sync(0xffffffffu, v,  off);
            int a2 = __shfl_up_sync(0xffffffffu, v2, off);
            if (lane >= off) { v += a; v2 += a2; }
        }
        swsum[lane] = v; swsum2[lane] = v2;
    }
    __syncthreads();
    int wb  = (w > 0) ? swsum[w - 1]  : 0;
    int wb2 = (w > 0) ? swsum2[w - 1] : 0;

    int run = wb + inc - sum;
    int offs[10];
#pragma unroll
    for (int k = 0; k < 10; k++) {
        offs[k] = run;
        if (base + k < NTOT) {
            g_offsets[base + k] = run;
            g_counts[base + k]  = c[k];
        }
        run += c[k];
    }
    int urun = wb2 + inc2 - usum;
#pragma unroll
    for (int k = 0; k < 10; k++) {
        if (base + k < NTOT && c[k] > 0) { g_ulist[urun] = base + k; urun++; }
    }
    if (t == 1023) g_U = wb2 + inc2;
    __syncthreads();

#pragma unroll
    for (int k = 0; k < 10; k++)
        if (base + k < NTOT) scnt[base + k] = offs[k];
    __syncthreads();

#pragma unroll
    for (int k = 0; k < 4; k++) {
        int i = t + k * 1024;
        int u = sidx[i];
        int pos = atomicAdd(&scnt[u], 1);
        sperm[pos] = i;
    }
    __syncthreads();

#pragma unroll
    for (int k = 0; k < 10; k++) {
        int u = base + k;
        if (u >= NTOT) continue;
        int n = c[k];
        if (n < 2) continue;
        int s0 = offs[k];
        for (int a = 1; a < n; a++) {
            int key = sperm[s0 + a];
            int b = a - 1;
            while (b >= 0 && sperm[s0 + b] > key) {
                sperm[s0 + b + 1] = sperm[s0 + b];
                b--;
            }
            sperm[s0 + b + 1] = key;
        }
    }
    __syncthreads();

#pragma unroll
    for (int k = 0; k < 4; k++) {
        int i = t + k * 1024;
        g_perm[i] = sperm[i];
    }
}

// ===== K2: per-unique aggregation: Z_u (bf16), s_u, c_u, fused MSE =====
__global__ void k_aggr(const float* __restrict__ yp, const float* __restrict__ yt) {
    int k = blockIdx.x;        // 0..BB-1
    int t = threadIdx.x;       // 128 threads, 4 cols each
    if (k == 0 && t == 0) g_tilecount = 0;   // reset reducer counter each replay
    int U = g_U;
    __nv_bfloat162* zOut = (__nv_bfloat162*)(g_Zb + (size_t)k * DD);
    if (k >= U) {
        __nv_bfloat162 z2; z2.x = __float2bfloat16(0.f); z2.y = z2.x;
        zOut[2 * t] = z2; zOut[2 * t + 1] = z2;
        if (t == 0) { g_s[k] = 0.f; g_c[k] = 0.f; g_ulist[k] = 0; g_msepart[k] = 0.f; }
        return;
    }
    int u = g_ulist[k];
    int s0 = g_offsets[u], cnt = g_counts[u];
    float ax = 0.f, ay = 0.f, az = 0.f, aw = 0.f, sq = 0.f, ms = 0.f;
    for (int a = 0; a < cnt; a++) {          // ordered -> deterministic
        int i = g_perm[s0 + a];
        float4 v = ((const float4*)(yp + (size_t)i * DD))[t];
        float4 w = ((const float4*)(yt + (size_t)i * DD))[t];
        ax += v.x; ay += v.y; az += v.z; aw += v.w;
        sq += v.x * v.x + v.y * v.y + v.z * v.z + v.w * v.w;
        float dx = v.x - w.x, dy = v.y - w.y, dz = v.z - w.z, dw = v.w - w.w;
        ms += dx * dx + dy * dy + dz * dz + dw * dw;
    }
    zOut[2 * t]     = __floats2bfloat162_rn(ax, ay);
    zOut[2 * t + 1] = __floats2bfloat162_rn(az, aw);
#pragma unroll
    for (int off = 16; off; off >>= 1) {
        sq += __shfl_down_sync(0xffffffffu, sq, off);
        ms += __shfl_down_sync(0xffffffffu, ms, off);
    }
    __shared__ float ssq[4], sms[4];
    int w = t >> 5, l = t & 31;
    if (l == 0) { ssq[w] = sq; sms[w] = ms; }
    __syncthreads();
    if (t == 0) {
        g_s[k] = ssq[0] + ssq[1] + ssq[2] + ssq[3];
        g_c[k] = (float)cnt;
        g_msepart[k] = sms[0] + sms[1] + sms[2] + sms[3];
    }
}

// == K3: fused Gram (bf16 mma) + hoisted gather; block 1024 = dedicated reducer ==
#define TM 128
#define TN 128
#define TK 32
#define NTILES 1024

// dynamic smem layout (bytes)
#define SA_OFF   0            // 2 stages x 8192
#define SB_OFF   16384        // 2 stages x 8192
#define SM_OFF   32768        // 128 x 136 bf16 = 34816
#define SC_OFF   67584        // 128 x 136 bf16 = 34816
#define SIU_OFF  102400       // 128 int
#define SJU_OFF  102912       // 128 int
#define SSQ_OFF  103424       // 128 float
#define SCC_OFF  103936       // 128 float
#define RED_OFF  104448       // 16 float
#define SMEM_BYTES 104512
#define SMP 68                // sM/sC row pitch in 32-bit words (136 bf16)

__device__ __forceinline__ void ldm_x4(unsigned r[4], unsigned addr) {
    asm volatile("ldmatrix.sync.aligned.m8n8.x4.shared.b16 {%0,%1,%2,%3}, [%4];"
                 : "=r"(r[0]), "=r"(r[1]), "=r"(r[2]), "=r"(r[3])
                 : "r"(addr));
}
__device__ __forceinline__ void mma16816(float c[4], const unsigned a[4],
                                         unsigned b0, unsigned b1) {
    asm volatile(
        "mma.sync.aligned.m16n8k16.row.col.f32.bf16.bf16.f32 "
        "{%0,%1,%2,%3}, {%4,%5,%6,%7}, {%8,%9}, {%0,%1,%2,%3};"
        : "+f"(c[0]), "+f"(c[1]), "+f"(c[2]), "+f"(c[3])
        : "r"(a[0]), "r"(a[1]), "r"(a[2]), "r"(a[3]), "r"(b0), "r"(b1));
}
__device__ __forceinline__ void cp16(unsigned saddr, const void* g) {
    asm volatile("cp.async.cg.shared.global [%0], [%1], 16;" :: "r"(saddr), "l"(g));
}
__device__ __forceinline__ void cp_commit() {
    asm volatile("cp.async.commit_group;");
}
template <int N> __device__ __forceinline__ void cp_wait() {
    asm volatile("cp.async.wait_group %0;" :: "n"(N));
}

// deterministic final reduce (256 threads), executed by the reducer block
__device__ void final_reduce(float* out, int out_size, int tid) {
    double m = 0.0, c = 0.0, e = 0.0;
#pragma unroll
    for (int k = 0; k < 4; k++) {            // fixed order -> deterministic
        m += (double)g_partM[tid + k * 256];
        c += (double)g_partC[tid + k * 256];
    }
#pragma unroll
    for (int k = 0; k < 16; k++)
        e += (double)g_msepart[tid + k * 256];
#pragma unroll
    for (int off = 16; off; off >>= 1) {
        m += __shfl_down_sync(0xffffffffu, m, off);
        c += __shfl_down_sync(0xffffffffu, c, off);
        e += __shfl_down_sync(0xffffffffu, e, off);
    }
    __shared__ double fsm[8], fsc[8], fse[8];
    int w = tid >> 5, l = tid & 31;
    if (l == 0) { fsm[w] = m; fsc[w] = c; fse[w] = e; }
    __syncthreads();
    if (tid == 0) {
        double M = 0.0, C = 0.0, E = 0.0;
#pragma unroll
        for (int i = 0; i < 8; i++) { M += fsm[i]; C += fsc[i]; E += fse[i]; }
        double mse = E / ((double)BB * (double)DD);
        double lml = M * 2.0 / ((double)BB * (double)BB);
        double lcl = C * 2.0 / ((double)BB * (double)BB);
        if (out_size > 0) out[0] = (float)(mse + 0.5 * lml - 0.5 * lcl);
        if (out_size > 1) out[1] = (float)lml;
        if (out_size > 2) out[2] = (float)lcl;
    }
}

__global__ __launch_bounds__(256, 2) void k_main(const float* __restrict__ ML,
                                                 const float* __restrict__ CL,
                                                 float* out, int out_size) {
    int tid = threadIdx.x;
    int bid = blockIdx.x;

    // ---- dedicated reducer block: branches off before any mainloop state ----
    if (bid == NTILES) {
        __shared__ unsigned sdone;
        if (tid == 0) {
            unsigned v;
            do {
                asm volatile("ld.global.acquire.gpu.u32 %0, [%1];"
                             : "=r"(v) : "l"(&g_tilecount));
                if (v < NTILES)
                    asm volatile("nanosleep.u32 200;");
            } while (v < NTILES);
            sdone = 1u;
        }
        __syncthreads();
        final_reduce(out, out_size, tid);
        return;
    }

    extern __shared__ __align__(16) char dsm[];
    unsigned sbase = (unsigned)__cvta_generic_to_shared(dsm);
    int*      sIu = (int*)(dsm + SIU_OFF);
    int*      sJu = (int*)(dsm + SJU_OFF);
    float*    sSq = (float*)(dsm + SSQ_OFF);
    float*    sCc = (float*)(dsm + SCC_OFF);
    float*    rM  = (float*)(dsm + RED_OFF);
    float*    rC  = rM + 8;
    unsigned* sMu = (unsigned*)(dsm + SM_OFF);   // bf16x2 words, pitch SMP
    unsigned* sCu = (unsigned*)(dsm + SC_OFF);

    int Ib = (bid >> 5) * TM;
    int Jb = (bid & 31) * TN;

    int U = g_U;
    if (Ib >= U || Jb >= U) {                  // tile entirely padding -> zero
        if (tid == 0) {
            g_partM[bid] = 0.f; g_partC[bid] = 0.f;
            __threadfence();
            atomicAdd(&g_tilecount, 1u);
        }
        return;
    }

    if (tid < TM) {
        sIu[tid] = g_ulist[Ib + tid];
        sSq[tid] = g_s[Ib + tid];
    } else {
        sJu[tid - TM] = g_ulist[Jb + tid - TM];
        sCc[tid - TM] = g_c[Jb + tid - TM];
    }
    __syncthreads();                           // indices visible for hoisted gather

    int wid = tid >> 5, lane = tid & 31;
    int wm = wid & 1;    // 0..1 -> 64 rows each
    int wn = wid >> 1;   // 0..3 -> 32 cols each

    float acc[4][4][4];
#pragma unroll
    for (int a = 0; a < 4; a++)
#pragma unroll
        for (int b = 0; b < 4; b++)
#pragma unroll
            for (int c = 0; c < 4; c++) acc[a][b][c] = 0.f;

    int lr = tid >> 2;  // 0..63
    int lc = tid & 3;   // 16B chunk within 64B row

    auto loadstage = [&](int it, int st) {
        int kk = it * TK;
        unsigned aS = sbase + SA_OFF + st * 8192;
        unsigned bS = sbase + SB_OFF + st * 8192;
#pragma unroll
        for (int h = 0; h < 2; h++) {
            int r = lr + h * 64;
            int pc = lc ^ ((r >> 1) & 3);
            cp16(aS + (unsigned)(r * 4 + pc) * 16u,
                 g_Zb + (size_t)(Ib + r) * DD + kk + lc * 8);
            cp16(bS + (unsigned)(r * 4 + pc) * 16u,
                 g_Zb + (size_t)(Jb + r) * DD + kk + lc * 8);
        }
        cp_commit();
    };

    loadstage(0, 0);

    for (int it = 0; it < 16; it++) {
        int st = it & 1;

        // ---- HOISTED gather issue: loads ride through barriers + cp_wait + MMA ----
        float mv[4], cv[4];
        int gr[2], gc[2];
#pragma unroll
        for (int q = 0; q < 2; q++) {
            int p = (it * 2 + q) * 256 + tid;
            int r = p >> 6, c2 = p & 63, c = c2 * 2;
            gr[q] = r; gc[q] = c2;
            size_t rowo = (size_t)sIu[r] * NTOT;
            int u0 = sJu[c], u1 = sJu[c + 1];
            mv[2 * q]     = __ldg(ML + rowo + u0);
            mv[2 * q + 1] = __ldg(ML + rowo + u1);
            cv[2 * q]     = __ldg(CL + rowo + u0);
            cv[2 * q + 1] = __ldg(CL + rowo + u1);
        }

        __syncthreads();
        if (it < 15) { loadstage(it + 1, st ^ 1); cp_wait<1>(); }
        else         { cp_wait<0>(); }
        __syncthreads();

        // ---- MMA on stage st (gather loads still in flight) ----
        unsigned aBase = sbase + SA_OFF + st * 8192;
        unsigned bBase = sbase + SB_OFF + st * 8192;
#pragma unroll
        for (int ks = 0; ks < 2; ks++) {
            unsigned af[4][4], bf[2][4];
            int chunk = ks * 2 + (lane >> 4);
#pragma unroll
            for (int ma = 0; ma < 4; ma++) {
                int row = wm * 64 + ma * 16 + (lane & 15);
                int pc = chunk ^ ((row >> 1) & 3);
                ldm_x4(af[ma], aBase + (unsigned)(row * 4 + pc) * 16u);
            }
#pragma unroll
            for (int nb = 0; nb < 2; nb++) {
                int row = wn * 32 + nb * 16 + (lane & 15);
                int pc = chunk ^ ((row >> 1) & 3);
                ldm_x4(bf[nb], bBase + (unsigned)(row * 4 + pc) * 16u);
            }
#pragma unroll
            for (int ma = 0; ma < 4; ma++)
#pragma unroll
                for (int na = 0; na < 4; na++) {
                    unsigned b0 = bf[na >> 1][(na & 1)];
                    unsigned b1 = bf[na >> 1][(na & 1) + 2];
                    mma16816(acc[ma][na], af[ma], b0, b1);
                }
        }

        // ---- stash gathered values (issued before the barriers) ----
#pragma unroll
        for (int q = 0; q < 2; q++) {
            __nv_bfloat162 m2 = __floats2bfloat162_rn(mv[2 * q], mv[2 * q + 1]);
            __nv_bfloat162 c2 = __floats2bfloat162_rn(cv[2 * q], cv[2 * q + 1]);
            sMu[gr[q] * SMP + gc[q]] = *(unsigned*)&m2;
            sCu[gr[q] * SMP + gc[q]] = *(unsigned*)&c2;
        }
    }
    __syncthreads();

    // ---- epilogue: d = c_v * s_u - Z_u.Z_v, operands from smem ----
    float aM = 0.f, aC = 0.f;
    int g = lane >> 2, tq = lane & 3;
#pragma unroll
    for (int ma = 0; ma < 4; ma++) {
        int r0 = wm * 64 + ma * 16 + g;
        int r1 = r0 + 8;
        float sq0 = sSq[r0], sq1 = sSq[r1];
#pragma unroll
        for (int na = 0; na < 4; na++) {
            int cw = wn * 16 + na * 4 + tq;   // 32-bit word column (= 2 bf16 cols)
            float cc0 = sCc[2 * cw], cc1 = sCc[2 * cw + 1];
            unsigned wm0 = sMu[r0 * SMP + cw];
            unsigned wm1 = sMu[r1 * SMP + cw];
            unsigned wc0 = sCu[r0 * SMP + cw];
            unsigned wc1 = sCu[r1 * SMP + cw];
            float2 fm0 = __bfloat1622float2(*(__nv_bfloat162*)&wm0);
            float2 fm1 = __bfloat1622float2(*(__nv_bfloat162*)&wm1);
            float2 fc0 = __bfloat1622float2(*(__nv_bfloat162*)&wc0);
            float2 fc1 = __bfloat1622float2(*(__nv_bfloat162*)&wc1);
            float d0 = cc0 * sq0 - acc[ma][na][0];
            float d1 = cc1 * sq0 - acc[ma][na][1];
            float d2 = cc0 * sq1 - acc[ma][na][2];
            float d3 = cc1 * sq1 - acc[ma][na][3];
            aM += fm0.x * d0 + fm0.y * d1 + fm1.x * d2 + fm1.y * d3;
            aC += fc0.x * d0 + fc0.y * d1 + fc1.x * d2 + fc1.y * d3;
        }
    }
#pragma unroll
    for (int off = 16; off; off >>= 1) {
        aM += __shfl_down_sync(0xffffffffu, aM, off);
        aC += __shfl_down_sync(0xffffffffu, aC, off);
    }
    if (lane == 0) { rM[wid] = aM; rC[wid] = aC; }
    __syncthreads();
    if (tid == 0) {
        float tMv = 0.f, tCv = 0.f;
#pragma unroll
        for (int w = 0; w < 8; w++) { tMv += rM[w]; tCv += rC[w]; }
        g_partM[bid] = tMv;
        g_partC[bid] = tCv;
        __threadfence();
        atomicAdd(&g_tilecount, 1u);
    }
}

// ================= launch =================
extern "C" void kernel_launch(void* const* d_in, const int* in_sizes, int n_in,
                              void* d_out, int out_size) {
    const float* yp = (const float*)d_in[0];
    const float* yt = (const float*)d_in[1];
    const int*   ix = (const int*)d_in[2];
    const float* ml = (const float*)d_in[3];
    const float* cl = (const float*)d_in[4];
    (void)in_sizes; (void)n_in;

    static bool attr_set = false;
    if (!attr_set) {
        cudaFuncSetAttribute(k_main, cudaFuncAttributeMaxDynamicSharedMemorySize,
                             SMEM_BYTES);
        cudaFuncSetAttribute(k_prep, cudaFuncAttributeMaxDynamicSharedMemorySize,
                             PREP_SMEM);
        attr_set = true;
    }

    k_prep<<<1, 1024, PREP_SMEM>>>(ix);
    k_aggr<<<BB, 128>>>(yp, yt);
    k_main<<<NTILES + 1, 256, SMEM_BYTES>>>(ml, cl, (float*)d_out, out_size);
}

// round 16
// speedup vs baseline: 1.1696x; 1.1696x over previous
#include <cuda_runtime.h>
#include <cuda_bf16.h>

// Problem constants
#define NTOT 10000
#define BB   4096
#define DD   512

// -------- scratch (device globals; no allocation allowed) --------
__device__ int   g_perm[BB];         // segment-grouped original rows (unsorted in segment)
__device__ int   g_ulist[BB];        // slot -> value (ascending by construction)
__device__ int   g_soff[BB];         // slot -> segment start in g_perm
__device__ int   g_scnt[BB];         // slot -> segment count
__device__ int   g_U;
__device__ float g_s[BB];            // per-unique sum of ||y_i||^2
__device__ float g_c[BB];            // per-unique count (float)
__device__ float g_msepart[BB];
__device__ float g_partM[1024];
__device__ float g_partC[1024];
__device__ unsigned g_tilecount;     // reset by k_aggr each replay
__device__ __align__(16) __nv_bfloat16 g_Zb[(size_t)BB * DD];  // aggregated embeddings

// ========== K1: diet preprocessing: hist + dual scan + atomic scatter ==========
#define PREP_SMEM ((NTOT + BB) * 4)

__global__ __launch_bounds__(1024, 1) void k_prep(const int* __restrict__ idx) {
    extern __shared__ int psm[];
    int* scnt = psm;             // counts, then reused as scatter cursors
    int* sidx = psm + NTOT;
    __shared__ int swsum[32], swsum2[32];

    int t = threadIdx.x;
    int lane = t & 31, w = t >> 5;

#pragma unroll
    for (int k = 0; k < 10; k++) {
        int i = t + k * 1024;
        if (i < NTOT) scnt[i] = 0;
    }
#pragma unroll
    for (int k = 0; k < 4; k++) sidx[t + k * 1024] = idx[t + k * 1024];
    __syncthreads();

    // histogram (smem atomics)
#pragma unroll
    for (int k = 0; k < 4; k++) atomicAdd(&scnt[sidx[t + k * 1024]], 1);
    __syncthreads();

    // each thread owns 10 consecutive values
    int base = t * 10;
    int c[10];
    int sum = 0, usum = 0;
#pragma unroll
    for (int k = 0; k < 10; k++) {
        int v = (base + k < NTOT) ? scnt[base + k] : 0;
        c[k] = v; sum += v; usum += (v > 0);
    }

    // dual warp-shuffle inclusive scans (positions + uniques)
    int inc = sum, inc2 = usum;
#pragma unroll
    for (int off = 1; off < 32; off <<= 1) {
        int v  = __shfl_up_sync(0xffffffffu, inc,  off);
        int v2 = __shfl_up_sync(0xffffffffu, inc2, off);
        if (lane >= off) { inc += v; inc2 += v2; }
    }
    if (lane == 31) { swsum[w] = inc; swsum2[w] = inc2; }
    __syncthreads();
    if (w == 0) {
        int v  = swsum[lane];
        int v2 = swsum2[lane];
#pragma unroll
        for (int off = 1; off < 32; off <<= 1) {
            int a  = __shfl_up_sync(0xffffffffu, v,  off);
            int a2 = __shfl_up_sync(0xffffffffu, v2, off);
            if (lane >= off) { v += a; v2 += a2; }
        }
        swsum[lane] = v; swsum2[lane] = v2;
    }
    __syncthreads();
    int wb  = (w > 0) ? swsum[w - 1]  : 0;
    int wb2 = (w > 0) ? swsum2[w - 1] : 0;

    int run  = wb + inc - sum;     // exclusive position prefix
    int urun = wb2 + inc2 - usum;  // exclusive unique prefix
    int offs[10];
#pragma unroll
    for (int k = 0; k < 10; k++) {
        offs[k] = run;
        int u = base + k;
        if (u < NTOT && c[k] > 0) {
            g_ulist[urun] = u;          // ascending by construction
            g_soff[urun]  = run;
            g_scnt[urun]  = c[k];
            urun++;
        }
        run += c[k];
    }
    if (t == 1023) g_U = wb2 + inc2;

    // cursors (each thread writes only its own slots; disjoint from others' reads)
#pragma unroll
    for (int k = 0; k < 10; k++)
        if (base + k < NTOT) scnt[base + k] = offs[k];
    __syncthreads();

    // atomic scatter straight to global g_perm (segment order resolved in k_aggr)
#pragma unroll
    for (int k = 0; k < 4; k++) {
        int i = t + k * 1024;
        int u = sidx[i];
        int pos = atomicAdd(&scnt[u], 1);
        g_perm[pos] = i;
    }
}

// ===== K2: per-unique aggregation with local segment sort; fused MSE =====
__global__ void k_aggr(const float* __restrict__ yp, const float* __restrict__ yt) {
    int k = blockIdx.x;        // slot 0..BB-1
    int t = threadIdx.x;       // 128 threads, 4 cols each
    if (k == 0 && t == 0) g_tilecount = 0;   // reset reducer counter each replay
    int U = g_U;
    __nv_bfloat162* zOut = (__nv_bfloat162*)(g_Zb + (size_t)k * DD);
    if (k >= U) {
        __nv_bfloat162 z2; z2.x = __float2bfloat16(0.f); z2.y = z2.x;
        zOut[2 * t] = z2; zOut[2 * t + 1] = z2;
        if (t == 0) { g_s[k] = 0.f; g_c[k] = 0.f; g_ulist[k] = 0; g_msepart[k] = 0.f; }
        return;
    }
    int s0 = g_soff[k], cnt = g_scnt[k];

    // deterministic order: sort this tiny segment ascending (thread 0, smem)
    __shared__ int seg[64];
    if (t == 0) {
        if (cnt <= 64) {
            for (int a = 0; a < cnt; a++) seg[a] = g_perm[s0 + a];
            for (int a = 1; a < cnt; a++) {
                int key = seg[a];
                int b = a - 1;
                while (b >= 0 && seg[b] > key) { seg[b + 1] = seg[b]; b--; }
                seg[b + 1] = key;
            }
        } else {  // cold correctness path: in-place global sort
            for (int a = 1; a < cnt; a++) {
                int key = g_perm[s0 + a];
                int b = a - 1;
                while (b >= 0 && g_perm[s0 + b] > key) {
                    g_perm[s0 + b + 1] = g_perm[s0 + b]; b--;
                }
                g_perm[s0 + b + 1] = key;
            }
        }
    }
    __syncthreads();

    float ax = 0.f, ay = 0.f, az = 0.f, aw = 0.f, sq = 0.f, ms = 0.f;
    for (int a = 0; a < cnt; a++) {          // sorted order -> deterministic
        int i = (cnt <= 64) ? seg[a] : g_perm[s0 + a];
        float4 v = ((const float4*)(yp + (size_t)i * DD))[t];
        float4 w = ((const float4*)(yt + (size_t)i * DD))[t];
        ax += v.x; ay += v.y; az += v.z; aw += v.w;
        sq += v.x * v.x + v.y * v.y + v.z * v.z + v.w * v.w;
        float dx = v.x - w.x, dy = v.y - w.y, dz = v.z - w.z, dw = v.w - w.w;
        ms += dx * dx + dy * dy + dz * dz + dw * dw;
    }
    zOut[2 * t]     = __floats2bfloat162_rn(ax, ay);
    zOut[2 * t + 1] = __floats2bfloat162_rn(az, aw);
#pragma unroll
    for (int off = 16; off; off >>= 1) {
        sq += __shfl_down_sync(0xffffffffu, sq, off);
        ms += __shfl_down_sync(0xffffffffu, ms, off);
    }
    __shared__ float ssq[4], sms[4];
    int w = t >> 5, l = t & 31;
    if (l == 0) { ssq[w] = sq; sms[w] = ms; }
    __syncthreads();
    if (t == 0) {
        g_s[k] = ssq[0] + ssq[1] + ssq[2] + ssq[3];
        g_c[k] = (float)g_scnt[k];
        g_msepart[k] = sms[0] + sms[1] + sms[2] + sms[3];
    }
}

// == K3: fused Gram (bf16 mma) + gather; block 1024 = dedicated reducer ==
// (byte-identical mainloop to the proven 118.7us R12 kernel)
#define TM 128
#define TN 128
#define TK 32
#define NTILES 1024

// dynamic smem layout (bytes)
#define SA_OFF   0            // 2 stages x 8192
#define SB_OFF   16384        // 2 stages x 8192
#define SM_OFF   32768        // 128 x 136 bf16 = 34816
#define SC_OFF   67584        // 128 x 136 bf16 = 34816
#define SIU_OFF  102400       // 128 int
#define SJU_OFF  102912       // 128 int
#define SSQ_OFF  103424       // 128 float
#define SCC_OFF  103936       // 128 float
#define RED_OFF  104448       // 16 float
#define SMEM_BYTES 104512
#define SMP 68                // sM/sC row pitch in 32-bit words (136 bf16)

__device__ __forceinline__ void ldm_x4(unsigned r[4], unsigned addr) {
    asm volatile("ldmatrix.sync.aligned.m8n8.x4.shared.b16 {%0,%1,%2,%3}, [%4];"
                 : "=r"(r[0]), "=r"(r[1]), "=r"(r[2]), "=r"(r[3])
                 : "r"(addr));
}
__device__ __forceinline__ void mma16816(float c[4], const unsigned a[4],
                                         unsigned b0, unsigned b1) {
    asm volatile(
        "mma.sync.aligned.m16n8k16.row.col.f32.bf16.bf16.f32 "
        "{%0,%1,%2,%3}, {%4,%5,%6,%7}, {%8,%9}, {%0,%1,%2,%3};"
        : "+f"(c[0]), "+f"(c[1]), "+f"(c[2]), "+f"(c[3])
        : "r"(a[0]), "r"(a[1]), "r"(a[2]), "r"(a[3]), "r"(b0), "r"(b1));
}
__device__ __forceinline__ void cp16(unsigned saddr, const void* g) {
    asm volatile("cp.async.cg.shared.global [%0], [%1], 16;" :: "r"(saddr), "l"(g));
}
__device__ __forceinline__ void cp_commit() {
    asm volatile("cp.async.commit_group;");
}
template <int N> __device__ __forceinline__ void cp_wait() {
    asm volatile("cp.async.wait_group %0;" :: "n"(N));
}

// deterministic final reduce (256 threads), executed by the reducer block
__device__ void final_reduce(float* out, int out_size, int tid) {
    double m = 0.0, c = 0.0, e = 0.0;
#pragma unroll
    for (int k = 0; k < 4; k++) {            // fixed order -> deterministic
        m += (double)g_partM[tid + k * 256];
        c += (double)g_partC[tid + k * 256];
    }
#pragma unroll
    for (int k = 0; k < 16; k++)
        e += (double)g_msepart[tid + k * 256];
#pragma unroll
    for (int off = 16; off; off >>= 1) {
        m += __shfl_down_sync(0xffffffffu, m, off);
        c += __shfl_down_sync(0xffffffffu, c, off);
        e += __shfl_down_sync(0xffffffffu, e, off);
    }
    __shared__ double fsm[8], fsc[8], fse[8];
    int w = tid >> 5, l = tid & 31;
    if (l == 0) { fsm[w] = m; fsc[w] = c; fse[w] = e; }
    __syncthreads();
    if (tid == 0) {
        double M = 0.0, C = 0.0, E = 0.0;
#pragma unroll
        for (int i = 0; i < 8; i++) { M += fsm[i]; C += fsc[i]; E += fse[i]; }
        double mse = E / ((double)BB * (double)DD);
        double lml = M * 2.0 / ((double)BB * (double)BB);
        double lcl = C * 2.0 / ((double)BB * (double)BB);
        if (out_size > 0) out[0] = (float)(mse + 0.5 * lml - 0.5 * lcl);
        if (out_size > 1) out[1] = (float)lml;
        if (out_size > 2) out[2] = (float)lcl;
    }
}

__global__ __launch_bounds__(256, 2) void k_main(const float* __restrict__ ML,
                                                 const float* __restrict__ CL,
                                                 float* out, int out_size) {
    int tid = threadIdx.x;
    int bid = blockIdx.x;

    // ---- dedicated reducer block: branches off before any mainloop state ----
    if (bid == NTILES) {
        __shared__ unsigned sdone;
        if (tid == 0) {
            unsigned v;
            do {
                asm volatile("ld.global.acquire.gpu.u32 %0, [%1];"
                             : "=r"(v) : "l"(&g_tilecount));
                if (v < NTILES)
                    asm volatile("nanosleep.u32 200;");
            } while (v < NTILES);
            sdone = 1u;
        }
        __syncthreads();
        final_reduce(out, out_size, tid);
        return;
    }

    extern __shared__ __align__(16) char dsm[];
    unsigned sbase = (unsigned)__cvta_generic_to_shared(dsm);
    int*      sIu = (int*)(dsm + SIU_OFF);
    int*      sJu = (int*)(dsm + SJU_OFF);
    float*    sSq = (float*)(dsm + SSQ_OFF);
    float*    sCc = (float*)(dsm + SCC_OFF);
    float*    rM  = (float*)(dsm + RED_OFF);
    float*    rC  = rM + 8;
    unsigned* sMu = (unsigned*)(dsm + SM_OFF);   // bf16x2 words, pitch SMP
    unsigned* sCu = (unsigned*)(dsm + SC_OFF);

    int Ib = (bid >> 5) * TM;
    int Jb = (bid & 31) * TN;

    int U = g_U;
    if (Ib >= U || Jb >= U) {                  // tile entirely padding -> zero
        if (tid == 0) {
            g_partM[bid] = 0.f; g_partC[bid] = 0.f;
            __threadfence();
            atomicAdd(&g_tilecount, 1u);
        }
        return;
    }

    if (tid < TM) {
        sIu[tid] = g_ulist[Ib + tid];
        sSq[tid] = g_s[Ib + tid];
    } else {
        sJu[tid - TM] = g_ulist[Jb + tid - TM];
        sCc[tid - TM] = g_c[Jb + tid - TM];
    }

    int wid = tid >> 5, lane = tid & 31;
    int wm = wid & 1;    // 0..1 -> 64 rows each
    int wn = wid >> 1;   // 0..3 -> 32 cols each

    float acc[4][4][4];
#pragma unroll
    for (int a = 0; a < 4; a++)
#pragma unroll
        for (int b = 0; b < 4; b++)
#pragma unroll
            for (int c = 0; c < 4; c++) acc[a][b][c] = 0.f;

    int lr = tid >> 2;  // 0..63
    int lc = tid & 3;   // 16B chunk within 64B row

    auto loadstage = [&](int it, int st) {
        int kk = it * TK;
        unsigned aS = sbase + SA_OFF + st * 8192;
        unsigned bS = sbase + SB_OFF + st * 8192;
#pragma unroll
        for (int h = 0; h < 2; h++) {
            int r = lr + h * 64;
            int pc = lc ^ ((r >> 1) & 3);
            cp16(aS + (unsigned)(r * 4 + pc) * 16u,
                 g_Zb + (size_t)(Ib + r) * DD + kk + lc * 8);
            cp16(bS + (unsigned)(r * 4 + pc) * 16u,
                 g_Zb + (size_t)(Jb + r) * DD + kk + lc * 8);
        }
        cp_commit();
    };

    loadstage(0, 0);

    for (int it = 0; it < 16; it++) {
        int st = it & 1;
        __syncthreads();
        if (it < 15) { loadstage(it + 1, st ^ 1); cp_wait<1>(); }
        else         { cp_wait<0>(); }
        __syncthreads();

        // ---- issue gather loads (coalesced: lanes = consecutive sorted cols) ----
        float mv[4], cv[4];
        int gr[2], gc[2];
#pragma unroll
        for (int q = 0; q < 2; q++) {
            int p = (it * 2 + q) * 256 + tid;
            int r = p >> 6, c2 = p & 63, c = c2 * 2;
            gr[q] = r; gc[q] = c2;
            size_t rowo = (size_t)sIu[r] * NTOT;
            int u0 = sJu[c], u1 = sJu[c + 1];
            mv[2 * q]     = __ldg(ML + rowo + u0);
            mv[2 * q + 1] = __ldg(ML + rowo + u1);
            cv[2 * q]     = __ldg(CL + rowo + u0);
            cv[2 * q + 1] = __ldg(CL + rowo + u1);
        }

        // ---- MMA on stage st (gather loads in flight) ----
        unsigned aBase = sbase + SA_OFF + st * 8192;
        unsigned bBase = sbase + SB_OFF + st * 8192;
#pragma unroll
        for (int ks = 0; ks < 2; ks++) {
            unsigned af[4][4], bf[2][4];
            int chunk = ks * 2 + (lane >> 4);
#pragma unroll
            for (int ma = 0; ma < 4; ma++) {
                int row = wm * 64 + ma * 16 + (lane & 15);
                int pc = chunk ^ ((row >> 1) & 3);
                ldm_x4(af[ma], aBase + (unsigned)(row * 4 + pc) * 16u);
            }
#pragma unroll
            for (int nb = 0; nb < 2; nb++) {
                int row = wn * 32 + nb * 16 + (lane & 15);
                int pc = chunk ^ ((row >> 1) & 3);
                ldm_x4(bf[nb], bBase + (unsigned)(row * 4 + pc) * 16u);
            }
#pragma unroll
            for (int ma = 0; ma < 4; ma++)
#pragma unroll
                for (int na = 0; na < 4; na++) {
                    unsigned b0 = bf[na >> 1][(na & 1)];
                    unsigned b1 = bf[na >> 1][(na & 1) + 2];
                    mma16816(acc[ma][na], af[ma], b0, b1);
                }
        }

        // ---- stash gathered values (arrived during MMA) ----
#pragma unroll
        for (int q = 0; q < 2; q++) {
            __nv_bfloat162 m2 = __floats2bfloat162_rn(mv[2 * q], mv[2 * q + 1]);
            __nv_bfloat162 c2 = __floats2bfloat162_rn(cv[2 * q], cv[2 * q + 1]);
            sMu[gr[q] * SMP + gc[q]] = *(unsigned*)&m2;
            sCu[gr[q] * SMP + gc[q]] = *(unsigned*)&c2;
        }
    }
    __syncthreads();

    // ---- epilogue: d = c_v * s_u - Z_u.Z_v, operands from smem ----
    float aM = 0.f, aC = 0.f;
    int g = lane >> 2, tq = lane & 3;
#pragma unroll
    for (int ma = 0; ma < 4; ma++) {
        int r0 = wm * 64 + ma * 16 + g;
        int r1 = r0 + 8;
        float sq0 = sSq[r0], sq1 = sSq[r1];
#pragma unroll
        for (int na = 0; na < 4; na++) {
            int cw = wn * 16 + na * 4 + tq;   // 32-bit word column (= 2 bf16 cols)
            float cc0 = sCc[2 * cw], cc1 = sCc[2 * cw + 1];
            unsigned wm0 = sMu[r0 * SMP + cw];
            unsigned wm1 = sMu[r1 * SMP + cw];
            unsigned wc0 = sCu[r0 * SMP + cw];
            unsigned wc1 = sCu[r1 * SMP + cw];
            float2 fm0 = __bfloat1622float2(*(__nv_bfloat162*)&wm0);
            float2 fm1 = __bfloat1622float2(*(__nv_bfloat162*)&wm1);
            float2 fc0 = __bfloat1622float2(*(__nv_bfloat162*)&wc0);
            float2 fc1 = __bfloat1622float2(*(__nv_bfloat162*)&wc1);
            float d0 = cc0 * sq0 - acc[ma][na][0];
            float d1 = cc1 * sq0 - acc[ma][na][1];
            float d2 = cc0 * sq1 - acc[ma][na][2];
            float d3 = cc1 * sq1 - acc[ma][na][3];
            aM += fm0.x * d0 + fm0.y * d1 + fm1.x * d2 + fm1.y * d3;
            aC += fc0.x * d0 + fc0.y * d1 + fc1.x * d2 + fc1.y * d3;
        }
    }
#pragma unroll
    for (int off = 16; off; off >>= 1) {
        aM += __shfl_down_sync(0xffffffffu, aM, off);
        aC += __shfl_down_sync(0xffffffffu, aC, off);
    }
    if (lane == 0) { rM[wid] = aM; rC[wid] = aC; }
    __syncthreads();
    if (tid == 0) {
        float tMv = 0.f, tCv = 0.f;
#pragma unroll
        for (int w = 0; w < 8; w++) { tMv += rM[w]; tCv += rC[w]; }
        g_partM[bid] = tMv;
        g_partC[bid] = tCv;
        __threadfence();
        atomicAdd(&g_tilecount, 1u);
    }
}

// ================= launch =================
extern "C" void kernel_launch(void* const* d_in, const int* in_sizes, int n_in,
                              void* d_out, int out_size) {
    const float* yp = (const float*)d_in[0];
    const float* yt = (const float*)d_in[1];
    const int*   ix = (const int*)d_in[2];
    const float* ml = (const float*)d_in[3];
    const float* cl = (const float*)d_in[4];
    (void)in_sizes; (void)n_in;

    static bool attr_set = false;
    if (!attr_set) {
        cudaFuncSetAttribute(k_main, cudaFuncAttributeMaxDynamicSharedMemorySize,
                             SMEM_BYTES);
        cudaFuncSetAttribute(k_prep, cudaFuncAttributeMaxDynamicSharedMemorySize,
                             PREP_SMEM);
        attr_set = true;
    }

    k_prep<<<1, 1024, PREP_SMEM>>>(ix);
    k_aggr<<<BB, 128>>>(yp, yt);
    k_main<<<NTILES + 1, 256, SMEM_BYTES>>>(ml, cl, (float*)d_out, out_size);
}

// round 17
// speedup vs baseline: 1.2039x; 1.0293x over previous
#include <cuda_runtime.h>
#include <cuda_bf16.h>

// Problem constants
#define NTOT 10000
#define BB   4096
#define DD   512

// -------- scratch (device globals; no allocation allowed) --------
__device__ int   g_perm[BB];         // segment-grouped original rows (unsorted in segment)
__device__ int   g_ulist[BB];        // slot -> value (ascending by construction)
__device__ int   g_soff[BB];         // slot -> segment start in g_perm
__device__ int   g_scnt[BB];         // slot -> segment count
__device__ int   g_U;
__device__ float g_s[BB];            // per-unique sum of ||y_i||^2
__device__ float g_c[BB];            // per-unique count (float)
__device__ float g_msepart[BB];
__device__ float g_partM[2048];
__device__ float g_partC[2048];
__device__ unsigned g_tilecount;     // reset by k_aggr each replay
__device__ __align__(16) __nv_bfloat16 g_Zb[(size_t)BB * DD];  // aggregated embeddings

// ========== K1: diet preprocessing: hist + dual scan + atomic scatter ==========
#define PREP_SMEM ((NTOT + BB) * 4)

__global__ __launch_bounds__(1024, 1) void k_prep(const int* __restrict__ idx) {
    extern __shared__ int psm[];
    int* scnt = psm;             // counts, then reused as scatter cursors
    int* sidx = psm + NTOT;
    __shared__ int swsum[32], swsum2[32];

    int t = threadIdx.x;
    int lane = t & 31, w = t >> 5;

#pragma unroll
    for (int k = 0; k < 10; k++) {
        int i = t + k * 1024;
        if (i < NTOT) scnt[i] = 0;
    }
#pragma unroll
    for (int k = 0; k < 4; k++) sidx[t + k * 1024] = idx[t + k * 1024];
    __syncthreads();

#pragma unroll
    for (int k = 0; k < 4; k++) atomicAdd(&scnt[sidx[t + k * 1024]], 1);
    __syncthreads();

    int base = t * 10;
    int c[10];
    int sum = 0, usum = 0;
#pragma unroll
    for (int k = 0; k < 10; k++) {
        int v = (base + k < NTOT) ? scnt[base + k] : 0;
        c[k] = v; sum += v; usum += (v > 0);
    }

    int inc = sum, inc2 = usum;
#pragma unroll
    for (int off = 1; off < 32; off <<= 1) {
        int v  = __shfl_up_sync(0xffffffffu, inc,  off);
        int v2 = __shfl_up_sync(0xffffffffu, inc2, off);
        if (lane >= off) { inc += v; inc2 += v2; }
    }
    if (lane == 31) { swsum[w] = inc; swsum2[w] = inc2; }
    __syncthreads();
    if (w == 0) {
        int v  = swsum[lane];
        int v2 = swsum2[lane];
#pragma unroll
        for (int off = 1; off < 32; off <<= 1) {
            int a  = __shfl_up_sync(0xffffffffu, v,  off);
            int a2 = __shfl_up_sync(0xffffffffu, v2, off);
            if (lane >= off) { v += a; v2 += a2; }
        }
        swsum[lane] = v; swsum2[lane] = v2;
    }
    __syncthreads();
    int wb  = (w > 0) ? swsum[w - 1]  : 0;
    int wb2 = (w > 0) ? swsum2[w - 1] : 0;

    int run  = wb + inc - sum;
    int urun = wb2 + inc2 - usum;
    int offs[10];
#pragma unroll
    for (int k = 0; k < 10; k++) {
        offs[k] = run;
        int u = base + k;
        if (u < NTOT && c[k] > 0) {
            g_ulist[urun] = u;
            g_soff[urun]  = run;
            g_scnt[urun]  = c[k];
            urun++;
        }
        run += c[k];
    }
    if (t == 1023) g_U = wb2 + inc2;

#pragma unroll
    for (int k = 0; k < 10; k++)
        if (base + k < NTOT) scnt[base + k] = offs[k];
    __syncthreads();

#pragma unroll
    for (int k = 0; k < 4; k++) {
        int i = t + k * 1024;
        int u = sidx[i];
        int pos = atomicAdd(&scnt[u], 1);
        g_perm[pos] = i;
    }
}

// ===== K2: per-unique aggregation with local segment sort; fused MSE =====
__global__ void k_aggr(const float* __restrict__ yp, const float* __restrict__ yt) {
    int k = blockIdx.x;        // slot 0..BB-1
    int t = threadIdx.x;       // 128 threads, 4 cols each
    if (k == 0 && t == 0) g_tilecount = 0;   // reset reducer counter each replay
    int U = g_U;
    __nv_bfloat162* zOut = (__nv_bfloat162*)(g_Zb + (size_t)k * DD);
    if (k >= U) {
        __nv_bfloat162 z2; z2.x = __float2bfloat16(0.f); z2.y = z2.x;
        zOut[2 * t] = z2; zOut[2 * t + 1] = z2;
        if (t == 0) { g_s[k] = 0.f; g_c[k] = 0.f; g_ulist[k] = 0; g_msepart[k] = 0.f; }
        return;
    }
    int s0 = g_soff[k], cnt = g_scnt[k];

    __shared__ int seg[64];
    if (t == 0) {
        if (cnt <= 64) {
            for (int a = 0; a < cnt; a++) seg[a] = g_perm[s0 + a];
            for (int a = 1; a < cnt; a++) {
                int key = seg[a];
                int b = a - 1;
                while (b >= 0 && seg[b] > key) { seg[b + 1] = seg[b]; b--; }
                seg[b + 1] = key;
            }
        } else {
            for (int a = 1; a < cnt; a++) {
                int key = g_perm[s0 + a];
                int b = a - 1;
                while (b >= 0 && g_perm[s0 + b] > key) {
                    g_perm[s0 + b + 1] = g_perm[s0 + b]; b--;
                }
                g_perm[s0 + b + 1] = key;
            }
        }
    }
    __syncthreads();

    float ax = 0.f, ay = 0.f, az = 0.f, aw = 0.f, sq = 0.f, ms = 0.f;
    for (int a = 0; a < cnt; a++) {
        int i = (cnt <= 64) ? seg[a] : g_perm[s0 + a];
        float4 v = ((const float4*)(yp + (size_t)i * DD))[t];
        float4 w = ((const float4*)(yt + (size_t)i * DD))[t];
        ax += v.x; ay += v.y; az += v.z; aw += v.w;
        sq += v.x * v.x + v.y * v.y + v.z * v.z + v.w * v.w;
        float dx = v.x - w.x, dy = v.y - w.y, dz = v.z - w.z, dw = v.w - w.w;
        ms += dx * dx + dy * dy + dz * dz + dw * dw;
    }
    zOut[2 * t]     = __floats2bfloat162_rn(ax, ay);
    zOut[2 * t + 1] = __floats2bfloat162_rn(az, aw);
#pragma unroll
    for (int off = 16; off; off >>= 1) {
        sq += __shfl_down_sync(0xffffffffu, sq, off);
        ms += __shfl_down_sync(0xffffffffu, ms, off);
    }
    __shared__ float ssq[4], sms[4];
    int w = t >> 5, l = t & 31;
    if (l == 0) { ssq[w] = sq; sms[w] = ms; }
    __syncthreads();
    if (t == 0) {
        g_s[k] = ssq[0] + ssq[1] + ssq[2] + ssq[3];
        g_c[k] = (float)g_scnt[k];
        g_msepart[k] = sms[0] + sms[1] + sms[2] + sms[3];
    }
}

// == K3: fused Gram (bf16 mma) + gather, TM=128 x TN=64 (3 CTAs/SM) ==
#define TM 128
#define TN 64
#define TK 32
#define NTILES 2048           // 32 I-tiles x 64 J-tiles

// dynamic smem layout (bytes)
#define SA_OFF   0            // 2 stages x 8192  (128 x 32 bf16)
#define SB_OFF   16384        // 2 stages x 4096  (64 x 32 bf16)
#define SM_OFF   24576        // 128 x 36 words = 18432
#define SC_OFF   43008        // 128 x 36 words = 18432
#define SIU_OFF  61440        // 128 int
#define SJU_OFF  61952        // 64 int
#define SSQ_OFF  62208        // 128 float
#define SCC_OFF  62720        // 64 float
#define RED_OFF  62976        // 16 float
#define SMEM_BYTES 63040
#define SMP 36                // stash row pitch in 32-bit words (72 bf16)

__device__ __forceinline__ void ldm_x4(unsigned r[4], unsigned addr) {
    asm volatile("ldmatrix.sync.aligned.m8n8.x4.shared.b16 {%0,%1,%2,%3}, [%4];"
                 : "=r"(r[0]), "=r"(r[1]), "=r"(r[2]), "=r"(r[3])
                 : "r"(addr));
}
__device__ __forceinline__ void mma16816(float c[4], const unsigned a[4],
                                         unsigned b0, unsigned b1) {
    asm volatile(
        "mma.sync.aligned.m16n8k16.row.col.f32.bf16.bf16.f32 "
        "{%0,%1,%2,%3}, {%4,%5,%6,%7}, {%8,%9}, {%0,%1,%2,%3};"
        : "+f"(c[0]), "+f"(c[1]), "+f"(c[2]), "+f"(c[3])
        : "r"(a[0]), "r"(a[1]), "r"(a[2]), "r"(a[3]), "r"(b0), "r"(b1));
}
__device__ __forceinline__ void cp16(unsigned saddr, const void* g) {
    asm volatile("cp.async.cg.shared.global [%0], [%1], 16;" :: "r"(saddr), "l"(g));
}
__device__ __forceinline__ void cp_commit() {
    asm volatile("cp.async.commit_group;");
}
template <int N> __device__ __forceinline__ void cp_wait() {
    asm volatile("cp.async.wait_group %0;" :: "n"(N));
}

// deterministic final reduce (256 threads), executed by the reducer block
__device__ void final_reduce(float* out, int out_size, int tid) {
    double m = 0.0, c = 0.0, e = 0.0;
#pragma unroll
    for (int k = 0; k < 8; k++) {            // fixed order -> deterministic
        m += (double)g_partM[tid + k * 256];
        c += (double)g_partC[tid + k * 256];
    }
#pragma unroll
    for (int k = 0; k < 16; k++)
        e += (double)g_msepart[tid + k * 256];
#pragma unroll
    for (int off = 16; off; off >>= 1) {
        m += __shfl_down_sync(0xffffffffu, m, off);
        c += __shfl_down_sync(0xffffffffu, c, off);
        e += __shfl_down_sync(0xffffffffu, e, off);
    }
    __shared__ double fsm[8], fsc[8], fse[8];
    int w = tid >> 5, l = tid & 31;
    if (l == 0) { fsm[w] = m; fsc[w] = c; fse[w] = e; }
    __syncthreads();
    if (tid == 0) {
        double M = 0.0, C = 0.0, E = 0.0;
#pragma unroll
        for (int i = 0; i < 8; i++) { M += fsm[i]; C += fsc[i]; E += fse[i]; }
        double mse = E / ((double)BB * (double)DD);
        double lml = M * 2.0 / ((double)BB * (double)BB);
        double lcl = C * 2.0 / ((double)BB * (double)BB);
        if (out_size > 0) out[0] = (float)(mse + 0.5 * lml - 0.5 * lcl);
        if (out_size > 1) out[1] = (float)lml;
        if (out_size > 2) out[2] = (float)lcl;
    }
}

__global__ __launch_bounds__(256, 3) void k_main(const float* __restrict__ ML,
                                                 const float* __restrict__ CL,
                                                 float* out, int out_size) {
    int tid = threadIdx.x;
    int bid = blockIdx.x;

    // ---- dedicated reducer block ----
    if (bid == NTILES) {
        __shared__ unsigned sdone;
        if (tid == 0) {
            unsigned v;
            do {
                asm volatile("ld.global.acquire.gpu.u32 %0, [%1];"
                             : "=r"(v) : "l"(&g_tilecount));
                if (v < NTILES)
                    asm volatile("nanosleep.u32 200;");
            } while (v < NTILES);
            sdone = 1u;
        }
        __syncthreads();
        final_reduce(out, out_size, tid);
        return;
    }

    extern __shared__ __align__(16) char dsm[];
    unsigned sbase = (unsigned)__cvta_generic_to_shared(dsm);
    int*      sIu = (int*)(dsm + SIU_OFF);
    int*      sJu = (int*)(dsm + SJU_OFF);
    float*    sSq = (float*)(dsm + SSQ_OFF);
    float*    sCc = (float*)(dsm + SCC_OFF);
    float*    rM  = (float*)(dsm + RED_OFF);
    float*    rC  = rM + 8;
    unsigned* sMu = (unsigned*)(dsm + SM_OFF);   // bf16x2 words, pitch SMP
    unsigned* sCu = (unsigned*)(dsm + SC_OFF);

    int Ib = (bid >> 6) * TM;     // 32 I-tiles
    int Jb = (bid & 63) * TN;     // 64 J-tiles

    int U = g_U;
    if (Ib >= U || Jb >= U) {                  // tile entirely padding -> zero
        if (tid == 0) {
            g_partM[bid] = 0.f; g_partC[bid] = 0.f;
            __threadfence();
            atomicAdd(&g_tilecount, 1u);
        }
        return;
    }

    if (tid < TM) {
        sIu[tid] = g_ulist[Ib + tid];
        sSq[tid] = g_s[Ib + tid];
    } else if (tid < TM + TN) {
        sJu[tid - TM] = g_ulist[Jb + tid - TM];
        sCc[tid - TM] = g_c[Jb + tid - TM];
    }

    int wid = tid >> 5, lane = tid & 31;
    int wm = wid & 1;    // 0..1 -> 64 rows each
    int wn = wid >> 1;   // 0..3 -> 16 cols each

    float acc[4][2][4];
#pragma unroll
    for (int a = 0; a < 4; a++)
#pragma unroll
        for (int b = 0; b < 2; b++)
#pragma unroll
            for (int c = 0; c < 4; c++) acc[a][b][c] = 0.f;

    int lr = tid >> 2;  // 0..63
    int lc = tid & 3;   // 16B chunk within 64B row

    auto loadstage = [&](int it, int st) {
        int kk = it * TK;
        unsigned aS = sbase + SA_OFF + st * 8192;
        unsigned bS = sbase + SB_OFF + st * 4096;
#pragma unroll
        for (int h = 0; h < 2; h++) {
            int r = lr + h * 64;
            int pc = lc ^ ((r >> 1) & 3);
            cp16(aS + (unsigned)(r * 4 + pc) * 16u,
                 g_Zb + (size_t)(Ib + r) * DD + kk + lc * 8);
        }
        {
            int r = lr;                        // 0..63
            int pc = lc ^ ((r >> 1) & 3);
            cp16(bS + (unsigned)(r * 4 + pc) * 16u,
                 g_Zb + (size_t)(Jb + r) * DD + kk + lc * 8);
        }
        cp_commit();
    };

    loadstage(0, 0);

    for (int it = 0; it < 16; it++) {
        int st = it & 1;
        __syncthreads();
        if (it < 15) { loadstage(it + 1, st ^ 1); cp_wait<1>(); }
        else         { cp_wait<0>(); }
        __syncthreads();

        // ---- gather: 1 word (2 cols) per thread per iter, coalesced cols ----
        float mv0, mv1, cv0, cv1;
        int p = it * 256 + tid;            // word index over 128x32
        int r = p >> 5, c2 = p & 31, c = c2 * 2;
        {
            size_t rowo = (size_t)sIu[r] * NTOT;
            int u0 = sJu[c], u1 = sJu[c + 1];
            mv0 = __ldg(ML + rowo + u0);
            mv1 = __ldg(ML + rowo + u1);
            cv0 = __ldg(CL + rowo + u0);
            cv1 = __ldg(CL + rowo + u1);
        }

        // ---- MMA on stage st (gather loads in flight) ----
        unsigned aBase = sbase + SA_OFF + st * 8192;
        unsigned bBase = sbase + SB_OFF + st * 4096;
#pragma unroll
        for (int ks = 0; ks < 2; ks++) {
            unsigned af[4][4], bf[4];
            int chunk = ks * 2 + (lane >> 4);
#pragma unroll
            for (int ma = 0; ma < 4; ma++) {
                int row = wm * 64 + ma * 16 + (lane & 15);
                int pc = chunk ^ ((row >> 1) & 3);
                ldm_x4(af[ma], aBase + (unsigned)(row * 4 + pc) * 16u);
            }
            {
                int row = wn * 16 + (lane & 15);
                int pc = chunk ^ ((row >> 1) & 3);
                ldm_x4(bf, bBase + (unsigned)(row * 4 + pc) * 16u);
            }
#pragma unroll
            for (int ma = 0; ma < 4; ma++)
#pragma unroll
                for (int na = 0; na < 2; na++) {
                    unsigned b0 = bf[na];        // k 0-7
                    unsigned b1 = bf[na + 2];    // k 8-15
                    mma16816(acc[ma][na], af[ma], b0, b1);
                }
        }

        // ---- stash gathered values (arrived during MMA) ----
        {
            __nv_bfloat162 m2 = __floats2bfloat162_rn(mv0, mv1);
            __nv_bfloat162 q2 = __floats2bfloat162_rn(cv0, cv1);
            sMu[r * SMP + c2] = *(unsigned*)&m2;
            sCu[r * SMP + c2] = *(unsigned*)&q2;
        }
    }
    __syncthreads();

    // ---- epilogue: d = c_v * s_u - Z_u.Z_v, operands from smem ----
    float aM = 0.f, aC = 0.f;
    int g = lane >> 2, tq = lane & 3;
#pragma unroll
    for (int ma = 0; ma < 4; ma++) {
        int r0 = wm * 64 + ma * 16 + g;
        int r1 = r0 + 8;
        float sq0 = sSq[r0], sq1 = sSq[r1];
#pragma unroll
        for (int na = 0; na < 2; na++) {
            int cw = wn * 8 + na * 4 + tq;    // word column (= 2 bf16 cols)
            float cc0 = sCc[2 * cw], cc1 = sCc[2 * cw + 1];
            unsigned wm0 = sMu[r0 * SMP + cw];
            unsigned wm1 = sMu[r1 * SMP + cw];
            unsigned wc0 = sCu[r0 * SMP + cw];
            unsigned wc1 = sCu[r1 * SMP + cw];
            float2 fm0 = __bfloat1622float2(*(__nv_bfloat162*)&wm0);
            float2 fm1 = __bfloat1622float2(*(__nv_bfloat162*)&wm1);
            float2 fc0 = __bfloat1622float2(*(__nv_bfloat162*)&wc0);
            float2 fc1 = __bfloat1622float2(*(__nv_bfloat162*)&wc1);
            float d0 = cc0 * sq0 - acc[ma][na][0];
            float d1 = cc1 * sq0 - acc[ma][na][1];
            float d2 = cc0 * sq1 - acc[ma][na][2];
            float d3 = cc1 * sq1 - acc[ma][na][3];
            aM += fm0.x * d0 + fm0.y * d1 + fm1.x * d2 + fm1.y * d3;
            aC += fc0.x * d0 + fc0.y * d1 + fc1.x * d2 + fc1.y * d3;
        }
    }
#pragma unroll
    for (int off = 16; off; off >>= 1) {
        aM += __shfl_down_sync(0xffffffffu, aM, off);
        aC += __shfl_down_sync(0xffffffffu, aC, off);
    }
    if (lane == 0) { rM[wid] = aM; rC[wid] = aC; }
    __syncthreads();
    if (tid == 0) {
        float tMv = 0.f, tCv = 0.f;
#pragma unroll
        for (int w = 0; w < 8; w++) { tMv += rM[w]; tCv += rC[w]; }
        g_partM[bid] = tMv;
        g_partC[bid] = tCv;
        __threadfence();
        atomicAdd(&g_tilecount, 1u);
    }
}

// ================= launch =================
extern "C" void kernel_launch(void* const* d_in, const int* in_sizes, int n_in,
                              void* d_out, int out_size) {
    const float* yp = (const float*)d_in[0];
    const float* yt = (const float*)d_in[1];
    const int*   ix = (const int*)d_in[2];
    const float* ml = (const float*)d_in[3];
    const float* cl = (const float*)d_in[4];
    (void)in_sizes; (void)n_in;

    static bool attr_set = false;
    if (!attr_set) {
        cudaFuncSetAttribute(k_main, cudaFuncAttributeMaxDynamicSharedMemorySize,
                             SMEM_BYTES);
        cudaFuncSetAttribute(k_prep, cudaFuncAttributeMaxDynamicSharedMemorySize,
                             PREP_SMEM);
        attr_set = true;
    }

    k_prep<<<1, 1024, PREP_SMEM>>>(ix);
    k_aggr<<<BB, 128>>>(yp, yt);
    k_main<<<NTILES + 1, 256, SMEM_BYTES>>>(ml, cl, (float*)d_out, out_size);
}